// round 5
// baseline (speedup 1.0000x reference)
#include <cuda_runtime.h>

// Shapes fixed by setup_inputs
#define RADIUS 3
constexpr int N_ = 2, C_ = 64, S_ = 4, H_ = 64, W_ = 44;
constexpr int P_  = H_ * W_;                // 2816
constexpr int SP_ = S_ * P_;                // 11264 (channel stride)

constexpr int TILE_Y  = 4;
constexpr int ROWS_SM = TILE_Y + 2 * RADIUS;   // 10
constexpr int WPAD    = 54;   // 27 8B-banks (odd) -> conflict-free tap LDS.64 phases
constexpr int W0PAD   = 48;   // f0 row pad: 12 16B-banks -> conflict-free LDS.128
constexpr int NPIX    = TILE_Y * W_;           // 176
constexpr int NQUAD   = 44;
constexpr int GSIZE   = 64;
constexpr int NGROUP  = 14;                    // 7 tap rows x 2 channel halves
constexpr int NTHREADS = GSIZE * NGROUP;       // 896 = 28 warps

constexpr int F1_ELEMS = C_ * ROWS_SM * WPAD;  // 34560 floats (135 KB)
constexpr int F0_ELEMS = C_ * TILE_Y * W0PAD;  // 12288 floats (48 KB)
constexpr int SMEM_BYTES = (F1_ELEMS + F0_ELEMS) * (int)sizeof(float); // 187392

using ull = unsigned long long;

__device__ __forceinline__ ull pk(float lo, float hi) {
    ull r; asm("mov.b64 %0, {%1, %2};" : "=l"(r) : "f"(lo), "f"(hi)); return r;
}
__device__ __forceinline__ void upk(float& lo, float& hi, ull v) {
    asm("mov.b64 {%0, %1}, %2;" : "=f"(lo), "=f"(hi) : "l"(v));
}
__device__ __forceinline__ void fma2(ull& d, ull a, ull b) {
    asm("fma.rn.f32x2 %0, %1, %2, %0;" : "+l"(d) : "l"(a), "l"(b));
}
__device__ __forceinline__ void add2(ull& d, ull a) {
    asm("add.rn.f32x2 %0, %0, %1;" : "+l"(d) : "l"(a));
}

__global__ __launch_bounds__(NTHREADS, 1)
void flow_kernel(const float* __restrict__ f0g, const float* __restrict__ f1g,
                 float* __restrict__ outg) {
    extern __shared__ float sm[];
    float* f1s = sm;                 // [C][ROWS_SM][WPAD], data cols 3..46
    float* f0s = sm + F1_ELEMS;      // [C][TILE_Y][W0PAD], data cols 0..43
    // aliases (dead-data reuse, guarded by syncs):
    float4* red4 = reinterpret_cast<float4*>(sm);                       // [7][176]
    ulonglong2* exch = reinterpret_cast<ulonglong2*>(sm + F1_ELEMS);    // [308][7]

    const int tid  = threadIdx.x;
    const int grp  = tid >> 6;           // 0..13
    const int s    = tid & 63;
    const int h    = grp / 7;            // channel half
    const int g    = grp % 7;            // tap row, dy = g-3
    // lane -> (yl, qx): conflict-free 16-lane LDS phases (verified R4)
    int yl, qx;
    if (s < 32) { yl = s >> 3;       qx = s & 7; }
    else        { int l = s - 32; yl = l / 3; qx = 8 + l % 3; }
    const bool active = (s < 44);

    const int b    = blockIdx.y;
    const int ni   = b >> 2;
    const int si   = b & 3;
    const int y0   = blockIdx.x * TILE_Y;
    const int base1 = ((ni * C_) * S_ + si) * P_;

    // ================= staging + halo zeroing (single phase, one sync) ======
    // x-halo: cols {0,1,2,47,48,49} x 10 rows x 64 ch  (cols 50..53 never read)
    for (int i = tid; i < 64 * 10 * 6; i += NTHREADS) {
        int c    = i / 60;
        int rem  = i - c * 60;
        int row  = rem / 6;
        int col6 = rem - row * 6;
        int col  = (col6 < 3) ? col6 : (44 + col6);
        f1s[(c * ROWS_SM + row) * WPAD + col] = 0.0f;
    }
    // y-halo rows on edge tiles only (cols 3..46 of invalid rows)
    if (y0 == 0 || y0 == (H_ - TILE_Y)) {
        const int r0 = (y0 == 0) ? 0 : 7;
        for (int i = tid; i < 64 * 3 * 44; i += NTHREADS) {
            int c   = i / 132;
            int rem = i - c * 132;
            int row = r0 + rem / 44;
            int col = 3 + (rem - (rem / 44) * 44);
            f1s[(c * ROWS_SM + row) * WPAD + col] = 0.0f;
        }
    }
    // stage f1: 220 float2 slots/ch, 16 ch/thread, div-free channel loop
    const float2* __restrict__ f1g2 = reinterpret_cast<const float2*>(f1g);
    const float2* __restrict__ f0g2 = reinterpret_cast<const float2*>(f0g);
    if (tid < 880) {
        const int slot = tid % 220;
        const int chb  = (tid / 220) * 16;
        const int row  = slot / 22;
        const int xu   = slot % 22;
        const int gy   = y0 - RADIUS + row;
        if ((unsigned)gy < (unsigned)H_) {
            int src = (base1 + gy * W_) / 2 + xu + chb * (SP_ / 2);
            int dst = (chb * ROWS_SM + row) * WPAD + 3 + 2 * xu;
            #pragma unroll 4
            for (int k = 0; k < 16; ++k) {
                float2 v = f1g2[src];
                f1s[dst] = v.x; f1s[dst + 1] = v.y;
                src += SP_ / 2; dst += ROWS_SM * WPAD;
            }
        }
    }
    // stage f0: 88 float2 slots/ch, 8 ch/thread
    if (tid < 704) {
        const int slot = tid % 88;
        const int chb  = (tid / 88) * 8;
        const int row  = slot / 22;
        const int xu   = slot % 22;
        int src = (base1 + (y0 + row) * W_) / 2 + xu + chb * (SP_ / 2);
        int dst = (chb * TILE_Y + row) * (W0PAD / 2) + xu;
        float2* __restrict__ f0s2 = reinterpret_cast<float2*>(f0s);
        #pragma unroll 4
        for (int k = 0; k < 8; ++k) {
            f0s2[dst] = f0g2[src];
            src += SP_ / 2; dst += TILE_Y * (W0PAD / 2);
        }
    }
    __syncthreads();

    // ================= main loop: 4 px x 7 taps x 32 ch, packed f32x2 =======
    // acc2[d]   : pixels (0,1), tap d ; acc2[7+d] : pixels (2,3), tap d
    ull acc2[14];
    #pragma unroll
    for (int i = 0; i < 14; ++i) acc2[i] = 0ull;

    if (active) {
        const float2* __restrict__ f1v = reinterpret_cast<const float2*>(f1s);
        const float4* __restrict__ f0q = reinterpret_cast<const float4*>(f0s);
        const float2* tap = f1v + ((h * 32) * ROWS_SM + yl + g) * (WPAD / 2) + 2 * qx;
        const float4* a4  = f0q + ((h * 32) * TILE_Y + yl) * (W0PAD / 4) + qx;

        #pragma unroll 2
        for (int c = 0; c < 32; ++c) {
            const float2 t0 = tap[0], t1 = tap[1], t2 = tap[2], t3 = tap[3], t4 = tap[4];
            const float4 A  = a4[0];
            // pair registers r[s] = (f1[s], f1[s+1]) for s = 0..8
            const ull r0 = pk(t0.x, t0.y), r2 = pk(t1.x, t1.y), r4 = pk(t2.x, t2.y),
                      r6 = pk(t3.x, t3.y), r8 = pk(t4.x, t4.y);
            const ull r1 = pk(t0.y, t1.x), r3 = pk(t1.y, t2.x),
                      r5 = pk(t2.y, t3.x), r7 = pk(t3.y, t4.x);
            const ull a0 = pk(A.x, A.y), a1 = pk(A.z, A.w);
            fma2(acc2[0],  a0, r0); fma2(acc2[1],  a0, r1);
            fma2(acc2[2],  a0, r2); fma2(acc2[3],  a0, r3);
            fma2(acc2[4],  a0, r4); fma2(acc2[5],  a0, r5);
            fma2(acc2[6],  a0, r6);
            fma2(acc2[7],  a1, r2); fma2(acc2[8],  a1, r3);
            fma2(acc2[9],  a1, r4); fma2(acc2[10], a1, r5);
            fma2(acc2[11], a1, r6); fma2(acc2[12], a1, r7);
            fma2(acc2[13], a1, r8);
            tap += ROWS_SM * (WPAD / 2);
            a4  += TILE_Y * (W0PAD / 4);
        }
    }
    __syncthreads();   // all f1s/f0s reads done; aliases writable

    const int widx = g * NQUAD + s;      // s < 44 when active
    if (active && h == 0) {
        #pragma unroll
        for (int j = 0; j < 7; ++j)
            exch[widx * 7 + j] = make_ulonglong2(acc2[2 * j], acc2[2 * j + 1]);
    }
    __syncthreads();

    if (active && h == 1) {
        #pragma unroll
        for (int j = 0; j < 7; ++j) {
            const ulonglong2 e = exch[widx * 7 + j];
            add2(acc2[2 * j], e.x);
            add2(acc2[2 * j + 1], e.y);
        }
        // unpack and compute masked per-row softmax stats (dy = g-3)
        float acc[28];
        #pragma unroll
        for (int d = 0; d < 7; ++d) {
            upk(acc[0 * 7 + d], acc[1 * 7 + d], acc2[d]);
            upk(acc[2 * 7 + d], acc[3 * 7 + d], acc2[7 + d]);
        }
        const bool rowv = ((unsigned)(y0 + yl + g - RADIUS) < (unsigned)H_);
        const int xl0 = 4 * qx;
        #pragma unroll
        for (int p = 0; p < 4; ++p) {
            const int xl = xl0 + p;
            float m = -1e30f;
            #pragma unroll
            for (int d = 0; d < 7; ++d) {
                const bool v = rowv && ((unsigned)(xl + d - RADIUS) < (unsigned)W_);
                if (v) m = fmaxf(m, acc[p * 7 + d]);
            }
            float ss = 0.0f, fx = 0.0f;
            #pragma unroll
            for (int d = 0; d < 7; ++d) {
                const bool v = rowv && ((unsigned)(xl + d - RADIUS) < (unsigned)W_);
                const float e = v ? __expf((acc[p * 7 + d] - m) * 0.125f) : 0.0f;
                ss += e;
                fx += e * (float)(d - RADIUS);
            }
            red4[g * NPIX + yl * W_ + xl] = make_float4(m, ss, fx, 0.0f);
        }
    }
    __syncthreads();

    // ================= combine 7 row-partials per pixel =====================
    if (tid < NPIX) {
        const int xl = tid % W_;
        const int yr = tid / W_;
        const int gy = y0 + yr;

        float4 p[7];
        #pragma unroll
        for (int gg = 0; gg < 7; ++gg) p[gg] = red4[gg * NPIX + tid];

        float M = p[0].x;
        #pragma unroll
        for (int gg = 1; gg < 7; ++gg) M = fmaxf(M, p[gg].x);

        float S = 0.0f, FX = 0.0f, FY = 0.0f;
        #pragma unroll
        for (int gg = 0; gg < 7; ++gg) {
            const float wg = __expf((p[gg].x - M) * 0.125f);  // empty row -> 0
            S  += p[gg].y * wg;
            FX += p[gg].z * wg;
            FY += p[gg].y * wg * (float)(gg - RADIUS);
        }
        const float inv = 1.0f / S;
        const int ob = ((ni * 2) * S_ + si) * P_ + gy * W_ + xl;
        outg[ob]       = FX * inv;
        outg[ob + SP_] = FY * inv;
    }
}

extern "C" void kernel_launch(void* const* d_in, const int* in_sizes, int n_in,
                              void* d_out, int out_size) {
    const float* f0 = (const float*)d_in[0];
    const float* f1 = (const float*)d_in[1];
    float* out = (float*)d_out;

    cudaFuncSetAttribute(flow_kernel,
                         cudaFuncAttributeMaxDynamicSharedMemorySize, SMEM_BYTES);

    dim3 grid(H_ / TILE_Y, N_ * S_);
    flow_kernel<<<grid, NTHREADS, SMEM_BYTES>>>(f0, f1, out);
}

// round 6
// speedup vs baseline: 1.0598x; 1.0598x over previous
#include <cuda_runtime.h>

// Shapes fixed by setup_inputs
#define RADIUS 3
constexpr int N_ = 2, C_ = 64, S_ = 4, H_ = 64, W_ = 44;
constexpr int P_  = H_ * W_;                // 2816
constexpr int SP_ = S_ * P_;                // 11264 (channel stride)

constexpr int TILE_Y  = 4;
constexpr int ROWS_SM = TILE_Y + 2 * RADIUS;   // 10
constexpr int WPAD    = 54;   // 27 8B-banks (odd) -> conflict-free tap LDS.64 phases
constexpr int W0PAD   = 48;   // f0 pad: 12 16B-banks -> conflict-free LDS.128
constexpr int NPIX    = TILE_Y * W_;           // 176
constexpr int NQUAD   = 44;
constexpr int GSIZE   = 64;
constexpr int NGROUP  = 14;                    // 7 tap rows x 2 channel halves
constexpr int NTHREADS = GSIZE * NGROUP;       // 896 = 28 warps
constexpr int NACT    = 7 * NQUAD;             // 308 active threads per half

constexpr int F1_ELEMS = C_ * ROWS_SM * WPAD;  // 34560 floats (135 KB)
constexpr int F0_ELEMS = C_ * TILE_Y * W0PAD;  // 12288 floats (48 KB)
constexpr int SMEM_BYTES = (F1_ELEMS + F0_ELEMS) * (int)sizeof(float); // 187392

using ull = unsigned long long;

__device__ __forceinline__ ull pkdup(float a) {
    ull r; asm("mov.b64 %0, {%1, %1};" : "=l"(r) : "f"(a)); return r;
}
__device__ __forceinline__ void upk(float& lo, float& hi, ull v) {
    asm("mov.b64 {%0, %1}, %2;" : "=f"(lo), "=f"(hi) : "l"(v));
}
__device__ __forceinline__ void fma2(ull& d, ull a, ull b) {
    asm("fma.rn.f32x2 %0, %1, %2, %0;" : "+l"(d) : "l"(a), "l"(b));
}
__device__ __forceinline__ void add2(ull& d, ull a) {
    asm("add.rn.f32x2 %0, %0, %1;" : "+l"(d) : "l"(a));
}

__global__ __launch_bounds__(NTHREADS, 1)
void flow_kernel(const float* __restrict__ f0g, const float* __restrict__ f1g,
                 float* __restrict__ outg) {
    extern __shared__ float sm[];
    float* f1s = sm;                 // [C][ROWS_SM][WPAD], data cols 3..46
    float* f0s = sm + F1_ELEMS;      // [C][TILE_Y][W0PAD], data cols 0..43
    // aliases (dead-data reuse, guarded by syncs):
    float4* red4 = reinterpret_cast<float4*>(sm);                 // [7][176]
    ull*    exA  = reinterpret_cast<ull*>(sm + F1_ELEMS);         // [12][NACT]
    float4* exB  = reinterpret_cast<float4*>(sm + F1_ELEMS + 2 * 12 * NACT); // [NACT]

    const int tid  = threadIdx.x;
    const int grp  = tid >> 6;           // 0..13
    const int s    = tid & 63;
    const int h    = grp / 7;            // channel half
    const int g    = grp % 7;            // tap row, dy = g-3
    // lane -> (yl, qx): conflict-free 16-lane LDS phases (verified R4)
    int yl, qx;
    if (s < 32) { yl = s >> 3;       qx = s & 7; }
    else        { int l = s - 32; yl = l / 3; qx = 8 + l % 3; }
    const bool active = (s < 44);

    const int b    = blockIdx.y;
    const int ni   = b >> 2;
    const int si   = b & 3;
    const int y0   = blockIdx.x * TILE_Y;
    const int base1 = ((ni * C_) * S_ + si) * P_;

    // ================= staging + halo zeroing (single phase, one sync) ======
    // x-halo: cols {0,1,2,47,48,49} x 10 rows x 64 ch (cols 50..53 never read)
    for (int i = tid; i < 64 * 10 * 6; i += NTHREADS) {
        int c    = i / 60;
        int rem  = i - c * 60;
        int row  = rem / 6;
        int col6 = rem - row * 6;
        int col  = (col6 < 3) ? col6 : (44 + col6);
        f1s[(c * ROWS_SM + row) * WPAD + col] = 0.0f;
    }
    // y-halo rows on edge tiles only (cols 3..46 of invalid rows)
    if (y0 == 0 || y0 == (H_ - TILE_Y)) {
        const int r0 = (y0 == 0) ? 0 : 7;
        for (int i = tid; i < 64 * 3 * 44; i += NTHREADS) {
            int c   = i / 132;
            int rem = i - c * 132;
            int row = r0 + rem / 44;
            int col = 3 + (rem - (rem / 44) * 44);
            f1s[(c * ROWS_SM + row) * WPAD + col] = 0.0f;
        }
    }
    // stage f1: 220 float2 slots/ch, 16 ch/thread, div-free channel loop
    const float2* __restrict__ f1g2 = reinterpret_cast<const float2*>(f1g);
    const float2* __restrict__ f0g2 = reinterpret_cast<const float2*>(f0g);
    if (tid < 880) {
        const int slot = tid % 220;
        const int chb  = (tid / 220) * 16;
        const int row  = slot / 22;
        const int xu   = slot % 22;
        const int gy   = y0 - RADIUS + row;
        if ((unsigned)gy < (unsigned)H_) {
            int src = (base1 + gy * W_) / 2 + xu + chb * (SP_ / 2);
            int dst = (chb * ROWS_SM + row) * WPAD + 3 + 2 * xu;
            #pragma unroll 8
            for (int k = 0; k < 16; ++k) {
                float2 v = f1g2[src];
                f1s[dst] = v.x; f1s[dst + 1] = v.y;
                src += SP_ / 2; dst += ROWS_SM * WPAD;
            }
        }
    }
    // stage f0: 88 float2 slots/ch, 8 ch/thread
    if (tid < 704) {
        const int slot = tid % 88;
        const int chb  = (tid / 88) * 8;
        const int row  = slot / 22;
        const int xu   = slot % 22;
        int src = (base1 + (y0 + row) * W_) / 2 + xu + chb * (SP_ / 2);
        int dst = (chb * TILE_Y + row) * (W0PAD / 2) + xu;
        float2* __restrict__ f0s2 = reinterpret_cast<float2*>(f0s);
        #pragma unroll 8
        for (int k = 0; k < 8; ++k) {
            f0s2[dst] = f0g2[src];
            src += SP_ / 2; dst += TILE_Y * (W0PAD / 2);
        }
    }
    __syncthreads();

    // ====== main loop: 4 px x 7 taps x 32 ch, tap-paired f32x2 (no repacks) ==
    // accP[px*3+j]: px even -> tap pairs (0,1)(2,3)(4,5); px odd -> (1,2)(3,4)(5,6)
    // accS[px]:     px even -> tap 6 ; px odd -> tap 0
    ull   accP[12];
    float accS[4];
    #pragma unroll
    for (int i = 0; i < 12; ++i) accP[i] = 0ull;
    #pragma unroll
    for (int i = 0; i < 4; ++i) accS[i] = 0.0f;

    if (active) {
        const ull* __restrict__ tap =
            reinterpret_cast<const ull*>(f1s) +
            ((h * 32) * ROWS_SM + yl + g) * (WPAD / 2) + 2 * qx;
        const float4* __restrict__ a4 =
            reinterpret_cast<const float4*>(f0s) +
            ((h * 32) * TILE_Y + yl) * (W0PAD / 4) + qx;

        #pragma unroll 2
        for (int c = 0; c < 32; ++c) {
            // P_s = (rv[s], rv[s+1]) straight from LDS.64
            const ull P0 = tap[0], P2 = tap[1], P4 = tap[2], P6 = tap[3], P8 = tap[4];
            const float4 A = a4[0];
            const ull aa0 = pkdup(A.x), aa1 = pkdup(A.y),
                      aa2 = pkdup(A.z), aa3 = pkdup(A.w);
            // scalar-tap operands: register-pair halves (no data movement)
            float t0lo, t0hi, t1lo, t1hi, t3lo, t3hi, t4lo, t4hi;
            upk(t0lo, t0hi, P0);   // rv1 = t0hi
            upk(t1lo, t1hi, P2);   // rv3 = t1hi
            upk(t3lo, t3hi, P6);   // rv6 = t3lo
            upk(t4lo, t4hi, P8);   // rv8 = t4lo

            fma2(accP[0],  aa0, P0);  // px0 taps(0,1)
            fma2(accP[1],  aa0, P2);  // px0 taps(2,3)
            fma2(accP[2],  aa0, P4);  // px0 taps(4,5)
            fma2(accP[3],  aa1, P2);  // px1 taps(1,2)
            fma2(accP[4],  aa1, P4);  // px1 taps(3,4)
            fma2(accP[5],  aa1, P6);  // px1 taps(5,6)
            fma2(accP[6],  aa2, P2);  // px2 taps(0,1)
            fma2(accP[7],  aa2, P4);  // px2 taps(2,3)
            fma2(accP[8],  aa2, P6);  // px2 taps(4,5)
            fma2(accP[9],  aa3, P4);  // px3 taps(1,2)
            fma2(accP[10], aa3, P6);  // px3 taps(3,4)
            fma2(accP[11], aa3, P8);  // px3 taps(5,6)
            accS[0] = fmaf(A.x, t3lo, accS[0]);  // px0 tap6 = rv6
            accS[1] = fmaf(A.y, t0hi, accS[1]);  // px1 tap0 = rv1
            accS[2] = fmaf(A.z, t4lo, accS[2]);  // px2 tap6 = rv8
            accS[3] = fmaf(A.w, t1hi, accS[3]);  // px3 tap0 = rv3

            tap += ROWS_SM * (WPAD / 2);
            a4  += TILE_Y * (W0PAD / 4);
        }
    }
    __syncthreads();   // all f1s/f0s reads done; aliases writable

    const int widx = g * NQUAD + s;      // < NACT when active
    if (active && h == 0) {
        #pragma unroll
        for (int j = 0; j < 12; ++j) exA[j * NACT + widx] = accP[j];  // 8B stride: conflict-free
        exB[widx] = make_float4(accS[0], accS[1], accS[2], accS[3]);
    }
    __syncthreads();

    if (active && h == 1) {
        #pragma unroll
        for (int j = 0; j < 12; ++j) add2(accP[j], exA[j * NACT + widx]);
        const float4 eb = exB[widx];
        accS[0] += eb.x; accS[1] += eb.y; accS[2] += eb.z; accS[3] += eb.w;

        // unpack to per-pixel taps
        float acc[4][7];
        upk(acc[0][0], acc[0][1], accP[0]);
        upk(acc[0][2], acc[0][3], accP[1]);
        upk(acc[0][4], acc[0][5], accP[2]);  acc[0][6] = accS[0];
        acc[1][0] = accS[1];
        upk(acc[1][1], acc[1][2], accP[3]);
        upk(acc[1][3], acc[1][4], accP[4]);
        upk(acc[1][5], acc[1][6], accP[5]);
        upk(acc[2][0], acc[2][1], accP[6]);
        upk(acc[2][2], acc[2][3], accP[7]);
        upk(acc[2][4], acc[2][5], accP[8]);  acc[2][6] = accS[2];
        acc[3][0] = accS[3];
        upk(acc[3][1], acc[3][2], accP[9]);
        upk(acc[3][3], acc[3][4], accP[10]);
        upk(acc[3][5], acc[3][6], accP[11]);

        // masked per-row softmax stats (dy = g-3)
        const bool rowv = ((unsigned)(y0 + yl + g - RADIUS) < (unsigned)H_);
        const int xl0 = 4 * qx;
        #pragma unroll
        for (int p = 0; p < 4; ++p) {
            const int xl = xl0 + p;
            float m = -1e30f;
            #pragma unroll
            for (int d = 0; d < 7; ++d) {
                const bool v = rowv && ((unsigned)(xl + d - RADIUS) < (unsigned)W_);
                if (v) m = fmaxf(m, acc[p][d]);
            }
            float ss = 0.0f, fx = 0.0f;
            #pragma unroll
            for (int d = 0; d < 7; ++d) {
                const bool v = rowv && ((unsigned)(xl + d - RADIUS) < (unsigned)W_);
                const float e = v ? __expf((acc[p][d] - m) * 0.125f) : 0.0f;
                ss += e;
                fx += e * (float)(d - RADIUS);
            }
            red4[g * NPIX + yl * W_ + xl] = make_float4(m, ss, fx, 0.0f);
        }
    }
    __syncthreads();

    // ================= combine 7 row-partials per pixel =====================
    if (tid < NPIX) {
        const int xl = tid % W_;
        const int yr = tid / W_;
        const int gy = y0 + yr;

        float4 p[7];
        #pragma unroll
        for (int gg = 0; gg < 7; ++gg) p[gg] = red4[gg * NPIX + tid];

        float M = p[0].x;
        #pragma unroll
        for (int gg = 1; gg < 7; ++gg) M = fmaxf(M, p[gg].x);

        float S = 0.0f, FX = 0.0f, FY = 0.0f;
        #pragma unroll
        for (int gg = 0; gg < 7; ++gg) {
            const float wg = __expf((p[gg].x - M) * 0.125f);  // empty row -> 0
            S  += p[gg].y * wg;
            FX += p[gg].z * wg;
            FY += p[gg].y * wg * (float)(gg - RADIUS);
        }
        const float inv = 1.0f / S;
        const int ob = ((ni * 2) * S_ + si) * P_ + gy * W_ + xl;
        outg[ob]       = FX * inv;
        outg[ob + SP_] = FY * inv;
    }
}

extern "C" void kernel_launch(void* const* d_in, const int* in_sizes, int n_in,
                              void* d_out, int out_size) {
    const float* f0 = (const float*)d_in[0];
    const float* f1 = (const float*)d_in[1];
    float* out = (float*)d_out;

    cudaFuncSetAttribute(flow_kernel,
                         cudaFuncAttributeMaxDynamicSharedMemorySize, SMEM_BYTES);

    dim3 grid(H_ / TILE_Y, N_ * S_);
    flow_kernel<<<grid, NTHREADS, SMEM_BYTES>>>(f0, f1, out);
}